// round 1
// baseline (speedup 1.0000x reference)
#include <cuda_runtime.h>
#include <math.h>
#include <stdint.h>

#define T_DIM 512
#define B_DIM 128
#define D_IN  128
#define H_DIM 512
#define R_DIM (T_DIM * B_DIM)   // 65536 rows for phase-1 GEMM

// ---------------- scratch (device globals: allocation-free) ----------------
__device__ __align__(16) float g_xp[(size_t)R_DIM * H_DIM];  // 128 MB: xp = x@W_ih^T + b_ih
__device__ __align__(16) float g_h0[B_DIM * H_DIM];          // zero initial state
__device__ int g_flags[128];                                  // persistent-kernel barrier flags

// ---------------- acquire/release helpers ----------------
__device__ __forceinline__ int ld_acq(const int* p) {
    int v;
    asm volatile("ld.global.acquire.gpu.b32 %0, [%1];" : "=r"(v) : "l"(p));
    return v;
}
__device__ __forceinline__ void st_rel(int* p, int v) {
    asm volatile("st.global.release.gpu.b32 [%0], %1;" :: "l"(p), "r"(v));
}

// ---------------- init: zero flags + h0 each replay ----------------
__global__ void init_kernel() {
    int i = blockIdx.x * blockDim.x + threadIdx.x;
    if (i < 128) g_flags[i] = 0;
    for (int idx = i; idx < B_DIM * H_DIM; idx += gridDim.x * blockDim.x)
        g_h0[idx] = 0.0f;
}

// ---------------- phase 1: xp = x @ W_ih^T + b_ih ----------------
// grid (R/64, H/64) = (1024, 8), block 256. Tile 64x64, K=128 in 2 chunks of 64.
// SMEM stores A,B transposed (k-major) so inner loop is 2x LDS.128 + 16 FMA.
__global__ void xp_kernel(const float* __restrict__ x,
                          const float* __restrict__ W,
                          const float* __restrict__ bias) {
    __shared__ float sA[64][68];   // sA[k][m], row stride 68 floats (16B aligned)
    __shared__ float sB[64][68];   // sB[k][n]

    const int tid = threadIdx.x;
    const int tx = tid & 15;         // n-group
    const int ty = tid >> 4;         // m-group
    const int rbase = blockIdx.x * 64;
    const int cbase = blockIdx.y * 64;

    float acc[4][4];
#pragma unroll
    for (int i = 0; i < 4; i++)
#pragma unroll
        for (int j = 0; j < 4; j++) acc[i][j] = 0.0f;

    for (int kb = 0; kb < D_IN; kb += 64) {
        // load 64 rows x 64 k (as 16 float4 per row) of both operands, transposed into SMEM
#pragma unroll
        for (int i = 0; i < 4; i++) {
            int idx = i * 256 + tid;       // 0..1023
            int row = idx >> 4;            // 0..63
            int k4  = idx & 15;            // float4 index along k
            float4 v = *(const float4*)&x[(size_t)(rbase + row) * D_IN + kb + k4 * 4];
            sA[k4 * 4 + 0][row] = v.x; sA[k4 * 4 + 1][row] = v.y;
            sA[k4 * 4 + 2][row] = v.z; sA[k4 * 4 + 3][row] = v.w;
            float4 w = *(const float4*)&W[(size_t)(cbase + row) * D_IN + kb + k4 * 4];
            sB[k4 * 4 + 0][row] = w.x; sB[k4 * 4 + 1][row] = w.y;
            sB[k4 * 4 + 2][row] = w.z; sB[k4 * 4 + 3][row] = w.w;
        }
        __syncthreads();
#pragma unroll
        for (int k = 0; k < 64; k++) {
            float4 a = *(const float4*)&sA[k][ty * 4];
            float4 b = *(const float4*)&sB[k][tx * 4];
            acc[0][0] = fmaf(a.x, b.x, acc[0][0]); acc[0][1] = fmaf(a.x, b.y, acc[0][1]);
            acc[0][2] = fmaf(a.x, b.z, acc[0][2]); acc[0][3] = fmaf(a.x, b.w, acc[0][3]);
            acc[1][0] = fmaf(a.y, b.x, acc[1][0]); acc[1][1] = fmaf(a.y, b.y, acc[1][1]);
            acc[1][2] = fmaf(a.y, b.z, acc[1][2]); acc[1][3] = fmaf(a.y, b.w, acc[1][3]);
            acc[2][0] = fmaf(a.z, b.x, acc[2][0]); acc[2][1] = fmaf(a.z, b.y, acc[2][1]);
            acc[2][2] = fmaf(a.z, b.z, acc[2][2]); acc[2][3] = fmaf(a.z, b.w, acc[2][3]);
            acc[3][0] = fmaf(a.w, b.x, acc[3][0]); acc[3][1] = fmaf(a.w, b.y, acc[3][1]);
            acc[3][2] = fmaf(a.w, b.z, acc[3][2]); acc[3][3] = fmaf(a.w, b.w, acc[3][3]);
        }
        __syncthreads();
    }

    float4 bj = *(const float4*)&bias[cbase + tx * 4];
#pragma unroll
    for (int i = 0; i < 4; i++) {
        float4 o;
        o.x = acc[i][0] + bj.x; o.y = acc[i][1] + bj.y;
        o.z = acc[i][2] + bj.z; o.w = acc[i][3] + bj.w;
        *(float4*)&g_xp[(size_t)(rbase + ty * 4 + i) * H_DIM + cbase + tx * 4] = o;
    }
}

// ---------------- phase 2: persistent recurrence ----------------
// 128 CTAs x 256 threads. CTA tile: 32 batch rows x 16 hidden cols.
// W_hh slice (16 cols x 512 k) stays resident in SMEM for all 512 steps.
// Per step: read full h_prev rows from L2 (written by everyone last step),
// FMA, tanh, write h_seq[t], then a release-flag grid barrier.
__global__ __launch_bounds__(256, 1)
void rnn_kernel(const float* __restrict__ Whh,
                const float* __restrict__ bhh,
                float* __restrict__ out) {
    __shared__ float sWt[512][16];  // sWt[k][j] : 32 KB, resident
    __shared__ float sH[32][128];   // one 128-wide k-chunk of the 32 h rows : 16 KB

    const int tid = threadIdx.x;
    const int bm = blockIdx.x & 3;         // 4 m-tiles of 32 rows
    const int bn = blockIdx.x >> 2;        // 32 n-tiles of 16 cols
    const int mbase = bm * 32;
    const int nbase = bn * 16;
    const int col = tid & 15;              // 0..15
    const int r0  = (tid >> 4) * 2;        // 0,2,...,30 : two rows per thread

    // load W slice transposed (one time)
    for (int idx = tid; idx < 512 * 16; idx += 256) {
        int k = idx & 511;
        int j = idx >> 9;
        sWt[k][j] = Whh[(size_t)(nbase + j) * H_DIM + k];
    }
    const float bias = bhh[nbase + col];
    __syncthreads();

    const float* hprev = g_h0;
    float* const hlast = out + (size_t)T_DIM * B_DIM * H_DIM;

    for (int t = 0; t < T_DIM; ++t) {
        float acc0 = 0.0f, acc1 = 0.0f;

        // prefetch first chunk of this step into registers
        float4 pre[4];
        {
#pragma unroll
            for (int i = 0; i < 4; i++) {
                int idx = i * 256 + tid;
                int row = idx >> 5;
                int kq  = idx & 31;
                pre[i] = __ldcg((const float4*)&hprev[(size_t)(mbase + row) * H_DIM + kq * 4]);
            }
        }

        for (int kb = 0; kb < H_DIM; kb += 128) {
            // store prefetched chunk to SMEM
#pragma unroll
            for (int i = 0; i < 4; i++) {
                int idx = i * 256 + tid;
                int row = idx >> 5;
                int kq  = idx & 31;
                *(float4*)&sH[row][kq * 4] = pre[i];
            }
            __syncthreads();
            // issue prefetch of next chunk (overlaps with compute below)
            if (kb + 128 < H_DIM) {
#pragma unroll
                for (int i = 0; i < 4; i++) {
                    int idx = i * 256 + tid;
                    int row = idx >> 5;
                    int kq  = idx & 31;
                    pre[i] = __ldcg((const float4*)&hprev[(size_t)(mbase + row) * H_DIM + kb + 128 + kq * 4]);
                }
            }
#pragma unroll
            for (int k = 0; k < 128; k += 4) {
                float4 h0v = *(const float4*)&sH[r0][k];
                float4 h1v = *(const float4*)&sH[r0 + 1][k];
                float w0 = sWt[kb + k + 0][col];
                float w1 = sWt[kb + k + 1][col];
                float w2 = sWt[kb + k + 2][col];
                float w3 = sWt[kb + k + 3][col];
                acc0 = fmaf(h0v.x, w0, acc0); acc1 = fmaf(h1v.x, w0, acc1);
                acc0 = fmaf(h0v.y, w1, acc0); acc1 = fmaf(h1v.y, w1, acc1);
                acc0 = fmaf(h0v.z, w2, acc0); acc1 = fmaf(h1v.z, w2, acc1);
                acc0 = fmaf(h0v.w, w3, acc0); acc1 = fmaf(h1v.w, w3, acc1);
            }
            __syncthreads();
        }

        // epilogue: add xp + bias, tanh, store h_seq[t]
        float* hout = out + (size_t)t * B_DIM * H_DIM;
        const size_t xbase = ((size_t)t * B_DIM + mbase + r0) * H_DIM + nbase + col;
        float xp0 = g_xp[xbase];
        float xp1 = g_xp[xbase + H_DIM];
        float v0 = tanhf(acc0 + xp0 + bias);
        float v1 = tanhf(acc1 + xp1 + bias);
        const size_t obase = (size_t)(mbase + r0) * H_DIM + nbase + col;
        hout[obase] = v0;
        hout[obase + H_DIM] = v1;
        if (t == T_DIM - 1) {
            hlast[obase] = v0;
            hlast[obase + H_DIM] = v1;
        }

        // grid barrier: release my flag, wait for all 128
        __threadfence();
        __syncthreads();
        if (tid == 0) st_rel(&g_flags[blockIdx.x], t + 1);
        if (tid < 128) {
            while (ld_acq(&g_flags[tid]) < t + 1) { __nanosleep(40); }
        }
        __syncthreads();

        hprev = hout;
    }
}

// ---------------- launch ----------------
extern "C" void kernel_launch(void* const* d_in, const int* in_sizes, int n_in,
                              void* d_out, int out_size) {
    const float* x    = (const float*)d_in[0];
    const float* W_ih = (const float*)d_in[1];
    const float* b_ih = (const float*)d_in[2];
    const float* W_hh = (const float*)d_in[3];
    const float* b_hh = (const float*)d_in[4];
    float* out = (float*)d_out;

    init_kernel<<<64, 256>>>();
    xp_kernel<<<dim3(R_DIM / 64, H_DIM / 64), 256>>>(x, W_ih, b_ih);
    rnn_kernel<<<128, 256>>>(W_hh, b_hh, out);
}

// round 2
// speedup vs baseline: 1.4326x; 1.4326x over previous
#include <cuda_runtime.h>
#include <math.h>
#include <stdint.h>

#define T_DIM 512
#define B_DIM 128
#define D_IN  128
#define H_DIM 512
#define R_DIM (T_DIM * B_DIM)   // 65536 rows for phase-1 GEMM

// ---------------- scratch (device globals: allocation-free) ----------------
__device__ __align__(16) float g_xp[(size_t)R_DIM * H_DIM];  // 128 MB: xp = x@W_ih^T + b_ih
__device__ int g_count;                                       // single barrier arrive counter

// ---------------- acquire/release helpers ----------------
__device__ __forceinline__ int ld_acq(const int* p) {
    int v;
    asm volatile("ld.global.acquire.gpu.b32 %0, [%1];" : "=r"(v) : "l"(p));
    return v;
}
__device__ __forceinline__ void red_rel_add(int* p, int v) {
    asm volatile("red.release.gpu.global.add.s32 [%0], %1;" :: "l"(p), "r"(v));
}

// ---------------- phase 1: xp = x @ W_ih^T + b_ih ----------------
// grid (R/64, H/64) = (1024, 8), block 256. Tile 64x64, K=128 in 2 chunks of 64.
// Block (0,0) thread 0 also resets the rnn barrier counter (ordering via stream).
__global__ void xp_kernel(const float* __restrict__ x,
                          const float* __restrict__ W,
                          const float* __restrict__ bias) {
    __shared__ float sA[64][68];   // sA[k][m]
    __shared__ float sB[64][68];   // sB[k][n]

    const int tid = threadIdx.x;
    if (blockIdx.x == 0 && blockIdx.y == 0 && tid == 0) g_count = 0;

    const int tx = tid & 15;         // n-group
    const int ty = tid >> 4;         // m-group
    const int rbase = blockIdx.x * 64;
    const int cbase = blockIdx.y * 64;

    float acc[4][4];
#pragma unroll
    for (int i = 0; i < 4; i++)
#pragma unroll
        for (int j = 0; j < 4; j++) acc[i][j] = 0.0f;

    for (int kb = 0; kb < D_IN; kb += 64) {
#pragma unroll
        for (int i = 0; i < 4; i++) {
            int idx = i * 256 + tid;       // 0..1023
            int row = idx >> 4;            // 0..63
            int k4  = idx & 15;            // float4 index along k
            float4 v = *(const float4*)&x[(size_t)(rbase + row) * D_IN + kb + k4 * 4];
            sA[k4 * 4 + 0][row] = v.x; sA[k4 * 4 + 1][row] = v.y;
            sA[k4 * 4 + 2][row] = v.z; sA[k4 * 4 + 3][row] = v.w;
            float4 w = *(const float4*)&W[(size_t)(cbase + row) * D_IN + kb + k4 * 4];
            sB[k4 * 4 + 0][row] = w.x; sB[k4 * 4 + 1][row] = w.y;
            sB[k4 * 4 + 2][row] = w.z; sB[k4 * 4 + 3][row] = w.w;
        }
        __syncthreads();
#pragma unroll
        for (int k = 0; k < 64; k++) {
            float4 a = *(const float4*)&sA[k][ty * 4];
            float4 b = *(const float4*)&sB[k][tx * 4];
            acc[0][0] = fmaf(a.x, b.x, acc[0][0]); acc[0][1] = fmaf(a.x, b.y, acc[0][1]);
            acc[0][2] = fmaf(a.x, b.z, acc[0][2]); acc[0][3] = fmaf(a.x, b.w, acc[0][3]);
            acc[1][0] = fmaf(a.y, b.x, acc[1][0]); acc[1][1] = fmaf(a.y, b.y, acc[1][1]);
            acc[1][2] = fmaf(a.y, b.z, acc[1][2]); acc[1][3] = fmaf(a.y, b.w, acc[1][3]);
            acc[2][0] = fmaf(a.z, b.x, acc[2][0]); acc[2][1] = fmaf(a.z, b.y, acc[2][1]);
            acc[2][2] = fmaf(a.z, b.z, acc[2][2]); acc[2][3] = fmaf(a.z, b.w, acc[2][3]);
            acc[3][0] = fmaf(a.w, b.x, acc[3][0]); acc[3][1] = fmaf(a.w, b.y, acc[3][1]);
            acc[3][2] = fmaf(a.w, b.z, acc[3][2]); acc[3][3] = fmaf(a.w, b.w, acc[3][3]);
        }
        __syncthreads();
    }

    float4 bj = *(const float4*)&bias[cbase + tx * 4];
#pragma unroll
    for (int i = 0; i < 4; i++) {
        float4 o;
        o.x = acc[i][0] + bj.x; o.y = acc[i][1] + bj.y;
        o.z = acc[i][2] + bj.z; o.w = acc[i][3] + bj.w;
        *(float4*)&g_xp[(size_t)(rbase + ty * 4 + i) * H_DIM + cbase + tx * 4] = o;
    }
}

// ---------------- phase 2: persistent recurrence ----------------
// 128 CTAs x 256 threads, 1 CTA/SM. CTA tile: 32 batch rows x 16 hidden cols.
// W_hh slice resident in SMEM. Per step: prefetch xp early, chunked h exchange
// via L2 with register prefetch, FMA, tanh, store h_seq[t], then a single-counter
// release/acquire grid barrier (one arriver + one poller per CTA).
__global__ __launch_bounds__(256, 1)
void rnn_kernel(const float* __restrict__ Whh,
                const float* __restrict__ bhh,
                float* __restrict__ out) {
    __shared__ float sWt[512][16];  // sWt[k][j] : 32 KB, resident
    __shared__ float sH[32][128];   // one 128-wide k-chunk of the 32 h rows : 16 KB

    const int tid = threadIdx.x;
    const int bm = blockIdx.x & 3;         // 4 m-tiles of 32 rows
    const int bn = blockIdx.x >> 2;        // 32 n-tiles of 16 cols
    const int mbase = bm * 32;
    const int nbase = bn * 16;
    const int col = tid & 15;              // 0..15
    const int r0  = (tid >> 4) * 2;        // 0,2,...,30 : two rows per thread

    // load W slice transposed (one time)
    for (int idx = tid; idx < 512 * 16; idx += 256) {
        int k = idx & 511;
        int j = idx >> 9;
        sWt[k][j] = Whh[(size_t)(nbase + j) * H_DIM + k];
    }
    const float bias = bhh[nbase + col];
    __syncthreads();

    float* const hlast = out + (size_t)T_DIM * B_DIM * H_DIM;

    for (int t = 0; t < T_DIM; ++t) {
        // prefetch xp for this step EARLY: DRAM latency hidden under the k-loop
        const size_t xbase = ((size_t)t * B_DIM + mbase + r0) * H_DIM + nbase + col;
        const float xp0 = __ldcg(&g_xp[xbase]);
        const float xp1 = __ldcg(&g_xp[xbase + H_DIM]);

        float acc0 = 0.0f, acc1 = 0.0f;

        if (t > 0) {
            const float* hprev = out + (size_t)(t - 1) * B_DIM * H_DIM;

            // prefetch first 128-wide k-chunk of this step's h rows
            float4 pre[4];
#pragma unroll
            for (int i = 0; i < 4; i++) {
                int idx = i * 256 + tid;
                int row = idx >> 5;
                int kq  = idx & 31;
                pre[i] = __ldcg((const float4*)&hprev[(size_t)(mbase + row) * H_DIM + kq * 4]);
            }

            for (int kb = 0; kb < H_DIM; kb += 128) {
#pragma unroll
                for (int i = 0; i < 4; i++) {
                    int idx = i * 256 + tid;
                    int row = idx >> 5;
                    int kq  = idx & 31;
                    *(float4*)&sH[row][kq * 4] = pre[i];
                }
                __syncthreads();
                if (kb + 128 < H_DIM) {
#pragma unroll
                    for (int i = 0; i < 4; i++) {
                        int idx = i * 256 + tid;
                        int row = idx >> 5;
                        int kq  = idx & 31;
                        pre[i] = __ldcg((const float4*)&hprev[(size_t)(mbase + row) * H_DIM + kb + 128 + kq * 4]);
                    }
                }
#pragma unroll
                for (int k = 0; k < 128; k += 4) {
                    float4 h0v = *(const float4*)&sH[r0][k];
                    float4 h1v = *(const float4*)&sH[r0 + 1][k];
                    float w0 = sWt[kb + k + 0][col];
                    float w1 = sWt[kb + k + 1][col];
                    float w2 = sWt[kb + k + 2][col];
                    float w3 = sWt[kb + k + 3][col];
                    acc0 = fmaf(h0v.x, w0, acc0); acc1 = fmaf(h1v.x, w0, acc1);
                    acc0 = fmaf(h0v.y, w1, acc0); acc1 = fmaf(h1v.y, w1, acc1);
                    acc0 = fmaf(h0v.z, w2, acc0); acc1 = fmaf(h1v.z, w2, acc1);
                    acc0 = fmaf(h0v.w, w3, acc0); acc1 = fmaf(h1v.w, w3, acc1);
                }
                __syncthreads();
            }
        }

        // epilogue: add xp + bias, tanh, store h_seq[t]
        float* hout = out + (size_t)t * B_DIM * H_DIM;
        float v0 = tanhf(acc0 + xp0 + bias);
        float v1 = tanhf(acc1 + xp1 + bias);
        const size_t obase = (size_t)(mbase + r0) * H_DIM + nbase + col;
        hout[obase] = v0;
        hout[obase + H_DIM] = v1;
        if (t == T_DIM - 1) {
            hlast[obase] = v0;
            hlast[obase + H_DIM] = v1;
        }

        // grid barrier (skip after final step): single-counter, single poller per CTA
        if (t < T_DIM - 1) {
            __syncthreads();               // all stores of this CTA's tile issued
            if (tid == 0) {
                red_rel_add(&g_count, 1);  // release: orders the h stores
                const int target = 128 * (t + 1);
                while (ld_acq(&g_count) < target) { __nanosleep(32); }
            }
            __syncthreads();               // broadcast barrier pass to CTA
        }
    }
}

// ---------------- launch ----------------
extern "C" void kernel_launch(void* const* d_in, const int* in_sizes, int n_in,
                              void* d_out, int out_size) {
    const float* x    = (const float*)d_in[0];
    const float* W_ih = (const float*)d_in[1];
    const float* b_ih = (const float*)d_in[2];
    const float* W_hh = (const float*)d_in[3];
    const float* b_hh = (const float*)d_in[4];
    float* out = (float*)d_out;

    xp_kernel<<<dim3(R_DIM / 64, H_DIM / 64), 256>>>(x, W_ih, b_ih);
    rnn_kernel<<<128, 256>>>(W_hh, b_hh, out);
}

// round 4
// speedup vs baseline: 1.5602x; 1.0891x over previous
#include <cuda_runtime.h>
#include <math.h>
#include <stdint.h>

#define T_DIM 512
#define B_DIM 128
#define D_IN  128
#define H_DIM 512
#define R_DIM (T_DIM * B_DIM)   // 65536 rows for phase-1 GEMM

// sW[16][516] + sH[32][516] floats, both padded +4 for bank-conflict-free access
#define WPAD 516
#define RNN_SMEM_BYTES ((16 * WPAD + 32 * WPAD) * 4)

// ---------------- scratch (device globals: allocation-free) ----------------
__device__ __align__(16) float g_xp[(size_t)R_DIM * H_DIM];  // 128 MB: xp = x@W_ih^T + b_ih
__device__ int g_count;                                       // single barrier arrive counter

// ---------------- acquire/release helpers ----------------
__device__ __forceinline__ int ld_acq(const int* p) {
    int v;
    asm volatile("ld.global.acquire.gpu.b32 %0, [%1];" : "=r"(v) : "l"(p));
    return v;
}
__device__ __forceinline__ void red_rel_add(int* p, int v) {
    asm volatile("red.release.gpu.global.add.s32 [%0], %1;" :: "l"(p), "r"(v));
}

// ---------------- phase 1: xp = x @ W_ih^T + b_ih ----------------
// grid (R/64, H/64) = (1024, 8), block 256. Tile 64x64, K=128 in 2 chunks of 64.
// Block (0,0) thread 0 also resets the rnn barrier counter (ordering via stream).
__global__ void xp_kernel(const float* __restrict__ x,
                          const float* __restrict__ W,
                          const float* __restrict__ bias) {
    __shared__ float sA[64][68];   // sA[k][m]
    __shared__ float sB[64][68];   // sB[k][n]

    const int tid = threadIdx.x;
    if (blockIdx.x == 0 && blockIdx.y == 0 && tid == 0) g_count = 0;

    const int tx = tid & 15;         // n-group
    const int ty = tid >> 4;         // m-group
    const int rbase = blockIdx.x * 64;
    const int cbase = blockIdx.y * 64;

    float acc[4][4];
#pragma unroll
    for (int i = 0; i < 4; i++)
#pragma unroll
        for (int j = 0; j < 4; j++) acc[i][j] = 0.0f;

    for (int kb = 0; kb < D_IN; kb += 64) {
#pragma unroll
        for (int i = 0; i < 4; i++) {
            int idx = i * 256 + tid;       // 0..1023
            int row = idx >> 4;            // 0..63
            int k4  = idx & 15;            // float4 index along k
            float4 v = *(const float4*)&x[(size_t)(rbase + row) * D_IN + kb + k4 * 4];
            sA[k4 * 4 + 0][row] = v.x; sA[k4 * 4 + 1][row] = v.y;
            sA[k4 * 4 + 2][row] = v.z; sA[k4 * 4 + 3][row] = v.w;
            float4 w = *(const float4*)&W[(size_t)(cbase + row) * D_IN + kb + k4 * 4];
            sB[k4 * 4 + 0][row] = w.x; sB[k4 * 4 + 1][row] = w.y;
            sB[k4 * 4 + 2][row] = w.z; sB[k4 * 4 + 3][row] = w.w;
        }
        __syncthreads();
#pragma unroll
        for (int k = 0; k < 64; k++) {
            float4 a = *(const float4*)&sA[k][ty * 4];
            float4 b = *(const float4*)&sB[k][tx * 4];
            acc[0][0] = fmaf(a.x, b.x, acc[0][0]); acc[0][1] = fmaf(a.x, b.y, acc[0][1]);
            acc[0][2] = fmaf(a.x, b.z, acc[0][2]); acc[0][3] = fmaf(a.x, b.w, acc[0][3]);
            acc[1][0] = fmaf(a.y, b.x, acc[1][0]); acc[1][1] = fmaf(a.y, b.y, acc[1][1]);
            acc[1][2] = fmaf(a.y, b.z, acc[1][2]); acc[1][3] = fmaf(a.y, b.w, acc[1][3]);
            acc[2][0] = fmaf(a.z, b.x, acc[2][0]); acc[2][1] = fmaf(a.z, b.y, acc[2][1]);
            acc[2][2] = fmaf(a.z, b.z, acc[2][2]); acc[2][3] = fmaf(a.z, b.w, acc[2][3]);
            acc[3][0] = fmaf(a.w, b.x, acc[3][0]); acc[3][1] = fmaf(a.w, b.y, acc[3][1]);
            acc[3][2] = fmaf(a.w, b.z, acc[3][2]); acc[3][3] = fmaf(a.w, b.w, acc[3][3]);
        }
        __syncthreads();
    }

    float4 bj = *(const float4*)&bias[cbase + tx * 4];
#pragma unroll
    for (int i = 0; i < 4; i++) {
        float4 o;
        o.x = acc[i][0] + bj.x; o.y = acc[i][1] + bj.y;
        o.z = acc[i][2] + bj.z; o.w = acc[i][3] + bj.w;
        *(float4*)&g_xp[(size_t)(rbase + ty * 4 + i) * H_DIM + cbase + tx * 4] = o;
    }
}

// ---------------- phase 2: persistent recurrence ----------------
// 128 CTAs x 256 threads, 1 CTA/SM. CTA tile: 32 batch rows x 16 hidden cols.
// sW[col][k] (transposed, padded) resident in SMEM -> w loads are LDS.128.
// Warp w only reads h rows 4w..4w+3: each warp stages its OWN rows
// (16 coalesced LDG.128 -> STS, __syncwarp only, no CTA sync needed).
// Inner loop per 4k: 3x LDS.128 (4 wavefronts/warp) + 8 FFMA -> FMA-floor bound.
__global__ __launch_bounds__(256, 1)
void rnn_kernel(const float* __restrict__ Whh,
                const float* __restrict__ bhh,
                float* __restrict__ out) {
    extern __shared__ float smem[];
    float* sW = smem;               // [16][WPAD]
    float* sH = smem + 16 * WPAD;   // [32][WPAD]

    const int tid  = threadIdx.x;
    const int lane = tid & 31;
    const int wrp  = tid >> 5;             // 0..7
    const int bm = blockIdx.x & 3;         // 4 m-tiles of 32 rows
    const int bn = blockIdx.x >> 2;        // 32 n-tiles of 16 cols
    const int mbase = bm * 32;
    const int nbase = bn * 16;
    const int col = tid & 15;              // 0..15
    const int r0  = (tid >> 4) * 2;        // 0,2,...,30 : two rows per thread

    // load W slice transposed into sW[col][k] (one time, coalesced both sides)
    for (int idx = tid; idx < 16 * 512; idx += 256) {
        int j = idx >> 9;          // col 0..15
        int k = idx & 511;
        sW[j * WPAD + k] = Whh[(size_t)(nbase + j) * H_DIM + k];
    }
    const float bias = bhh[nbase + col];
    __syncthreads();

    float* const hlast = out + (size_t)T_DIM * B_DIM * H_DIM;
    const float* hA = &sH[(size_t)r0 * WPAD];
    const float* hB = &sH[(size_t)(r0 + 1) * WPAD];
    const float* wp = &sW[(size_t)col * WPAD];

    // precomputed staging geometry: warp stages rows 4w..4w+3.
    // lane i covers float4 f = j*32 + lane (j=0..15); row = f>>7, c4 = f&127.
    // For fixed lane, f>>7 and f&127 follow a simple pattern; precompute bases.
    const int stg_row0 = wrp * 4;                         // first staged row of this warp
    // global base of this warp's first staged row (element units)
    // sH base for staged writes
    float* const sH_w = &sH[(size_t)stg_row0 * WPAD];

    for (int t = 0; t < T_DIM; ++t) {
        // prefetch xp for this step EARLY (DRAM latency hidden under the k-loop)
        const size_t xbase = ((size_t)t * B_DIM + mbase + r0) * H_DIM + nbase + col;
        const float xp0 = __ldcg(&g_xp[xbase]);
        const float xp1 = __ldcg(&g_xp[xbase + H_DIM]);

        float acc0 = 0.0f, acc1 = 0.0f;

        if (t > 0) {
            const float* hprev = out + (size_t)(t - 1) * B_DIM * H_DIM
                               + (size_t)(mbase + stg_row0) * H_DIM;

            // per-warp staging: this warp's 4 rows = 2048 floats = 512 float4.
            // lane covers float4 indices lane, lane+32, ..., lane+480 (row = f>>7).
            float4 pre[16];
#pragma unroll
            for (int i = 0; i < 16; i++) {
                int f = i * 32 + lane;
                pre[i] = __ldcg((const float4*)hprev + f);
            }
#pragma unroll
            for (int i = 0; i < 16; i++) {
                int f   = i * 32 + lane;
                int row = f >> 7;          // 0..3 within warp's group
                int c4  = f & 127;
                *(float4*)&sH_w[(size_t)row * WPAD + c4 * 4] = pre[i];
            }
            __syncwarp();   // each warp reads only its own staged rows

#pragma unroll 16
            for (int k = 0; k < H_DIM; k += 4) {
                float4 a = *(const float4*)(hA + k);
                float4 b = *(const float4*)(hB + k);
                float4 w = *(const float4*)(wp + k);
                acc0 = fmaf(a.x, w.x, acc0); acc1 = fmaf(b.x, w.x, acc1);
                acc0 = fmaf(a.y, w.y, acc0); acc1 = fmaf(b.y, w.y, acc1);
                acc0 = fmaf(a.z, w.z, acc0); acc1 = fmaf(b.z, w.z, acc1);
                acc0 = fmaf(a.w, w.w, acc0); acc1 = fmaf(b.w, w.w, acc1);
            }
        }

        // epilogue: add xp + bias, tanh, store h_seq[t]
        float* hout = out + (size_t)t * B_DIM * H_DIM;
        float v0 = tanhf(acc0 + xp0 + bias);
        float v1 = tanhf(acc1 + xp1 + bias);
        const size_t obase = (size_t)(mbase + r0) * H_DIM + nbase + col;
        hout[obase] = v0;
        hout[obase + H_DIM] = v1;
        if (t == T_DIM - 1) {
            hlast[obase] = v0;
            hlast[obase + H_DIM] = v1;
        }

        // grid barrier (skip after final step): single counter, single poller per CTA
        if (t < T_DIM - 1) {
            __syncthreads();               // all stores of this CTA's tile issued
            if (tid == 0) {
                red_rel_add(&g_count, 1);  // release: orders the h stores
                const int target = 128 * (t + 1);
                while (ld_acq(&g_count) < target) { __nanosleep(32); }
            }
            __syncthreads();               // broadcast barrier pass to CTA
        }
    }
}

// ---------------- launch ----------------
extern "C" void kernel_launch(void* const* d_in, const int* in_sizes, int n_in,
                              void* d_out, int out_size) {
    const float* x    = (const float*)d_in[0];
    const float* W_ih = (const float*)d_in[1];
    const float* b_ih = (const float*)d_in[2];
    const float* W_hh = (const float*)d_in[3];
    const float* b_hh = (const float*)d_in[4];
    float* out = (float*)d_out;

    // sticky per-function attribute; idempotent, set before the first launch
    cudaFuncSetAttribute(rnn_kernel, cudaFuncAttributeMaxDynamicSharedMemorySize,
                         RNN_SMEM_BYTES);

    xp_kernel<<<dim3(R_DIM / 64, H_DIM / 64), 256>>>(x, W_ih, b_ih);
    rnn_kernel<<<128, 256, RNN_SMEM_BYTES>>>(W_hh, b_hh, out);
}